// round 2
// baseline (speedup 1.0000x reference)
#include <cuda_runtime.h>
#include <math_constants.h>

// EMDLoss (Sinkhorn, eps=0.005, 50 iters), B=8, N=2048, dim=3.
// Factored cost C = pp + qq - 2 p.q; all Sinkhorn math in log2 domain with
// scale S2 = 1/(eps*ln2). Rows keep RAW coords (w = |p|^2*S2); the j-table
// is scaled by 2*S2 at load time, so dot(r, tbl) carries exactly one factor
// of 2*S2. Online truncated log2-sum-exp with warp-shared running max.

#define BB 8
#define NN 2048

static __device__ float4 d_P4[BB * NN];   // (px, py, pz, |p|^2 * S2)
static __device__ float4 d_Q4[BB * NN];
static __device__ float  d_f[BB * NN];
static __device__ float  d_g[BB * NN];
static __device__ float  d_partials[512];

__device__ __forceinline__ float ex2f_(float x) {
    float r; asm("ex2.approx.f32 %0, %1;" : "=f"(r) : "f"(x)); return r;
}
__device__ __forceinline__ float lg2f_(float x) {
    float r; asm("lg2.approx.f32 %0, %1;" : "=f"(r) : "f"(x)); return r;
}

// constants
#define S2F      288.5390081777927f      // 1/(eps*ln2)
#define S2X2     577.0780163555854f      // 2/(eps*ln2)
#define EPSLN2   0.0034657359027997f     // eps*ln2
#define EPSLOGMU (-0.03812309493079699f) // eps * (-ln N)
#define TT       25.0f                   // log2-domain truncation threshold

// ---------------------------------------------------------------------------
__global__ void prep_kernel(const float* __restrict__ preds,
                            const float* __restrict__ gts) {
    int b = blockIdx.x;
    for (int i = threadIdx.x; i < NN; i += blockDim.x) {
        int idx = b * NN + i;
        const float* p = preds + idx * 3;
        float x = p[0], y = p[1], z = p[2];
        d_P4[idx] = make_float4(x, y, z, (x * x + y * y + z * z) * S2F);
        d_f[idx] = 0.f;
        const float* q = gts + idx * 3;
        x = q[0]; y = q[1]; z = q[2];
        d_Q4[idx] = make_float4(x, y, z, (x * x + y * y + z * z) * S2F);
        d_g[idx] = 0.f;
    }
}

// Full online update for one row: warp-shared running max + rescale.
#define FULLROW(m, s, mt, a)                                        \
    {                                                               \
        float c = fmaxf(m, a);                                      \
        c = fmaxf(c, __shfl_xor_sync(0xffffffffu, c, 16));          \
        c = fmaxf(c, __shfl_xor_sync(0xffffffffu, c, 8));           \
        c = fmaxf(c, __shfl_xor_sync(0xffffffffu, c, 4));           \
        c = fmaxf(c, __shfl_xor_sync(0xffffffffu, c, 2));           \
        c = fmaxf(c, __shfl_xor_sync(0xffffffffu, c, 1));           \
        s = fmaf(s, ex2f_(m - c), ex2f_(a - c));                    \
        m = c; mt = c - TT;                                         \
    }

#define MERGEROW(m, s, off)                                         \
    {                                                               \
        float mo = __shfl_xor_sync(0xffffffffu, m, off);            \
        float so = __shfl_xor_sync(0xffffffffu, s, off);            \
        float mn = fmaxf(m, mo);                                    \
        s = fmaf(so, ex2f_(mo - mn), s * ex2f_(m - mn));            \
        m = mn;                                                     \
    }

// One Sinkhorn half-update. dir=0: update f (rows=preds, reduce over gts/g).
//                           dir=1: update g (rows=gts,  reduce over preds/f).
__global__ void __launch_bounds__(256) half_kernel(int dir) {
    int blk = blockIdx.x;
    int b = blk >> 6;          // 64 chunks per batch
    int chunk = blk & 63;

    const float4* R4  = dir ? d_Q4 : d_P4;
    const float4* D4  = dir ? d_P4 : d_Q4;
    const float*  pin = dir ? d_f  : d_g;
    float*        pout = dir ? d_g : d_f;

    __shared__ float4 tbl[NN];
    {
        const float4* Db = D4 + b * NN;
        const float*  pb = pin + b * NN;
        for (int j = threadIdx.x; j < NN; j += 256) {
            float4 q = Db[j];
            float4 t;
            t.x = q.x * S2X2;
            t.y = q.y * S2X2;
            t.z = q.z * S2X2;
            t.w = fmaf(pb[j], S2F, -q.w);   // pot_j*S2 - |q|^2*S2
            tbl[j] = t;
        }
    }
    __syncthreads();

    int warp = threadIdx.x >> 5;
    int lane = threadIdx.x & 31;
    int row0 = b * NN + chunk * 32 + warp * 4;

    float4 r0 = R4[row0 + 0];
    float4 r1 = R4[row0 + 1];
    float4 r2 = R4[row0 + 2];
    float4 r3 = R4[row0 + 3];

    const float NEGINF = -CUDART_INF_F;
    float m0 = NEGINF, m1 = NEGINF, m2 = NEGINF, m3 = NEGINF;
    float s0 = 0.f, s1 = 0.f, s2 = 0.f, s3 = 0.f;
    float mt0 = NEGINF, mt1 = NEGINF, mt2 = NEGINF, mt3 = NEGINF;

#pragma unroll 2
    for (int k = 0; k < 64; ++k) {
        float4 q = tbl[(k << 5) + lane];
        float a0 = fmaf(r0.x, q.x, fmaf(r0.y, q.y, fmaf(r0.z, q.z, q.w)));
        float a1 = fmaf(r1.x, q.x, fmaf(r1.y, q.y, fmaf(r1.z, q.z, q.w)));
        float a2 = fmaf(r2.x, q.x, fmaf(r2.y, q.y, fmaf(r2.z, q.z, q.w)));
        float a3 = fmaf(r3.x, q.x, fmaf(r3.y, q.y, fmaf(r3.z, q.z, q.w)));
        float e0 = a0 - mt0;
        float e1 = a1 - mt1;
        float e2 = a2 - mt2;
        float e3 = a3 - mt3;
        float emax = fmaxf(fmaxf(e0, e1), fmaxf(e2, e3));
        if (__any_sync(0xffffffffu, emax > 0.f)) {
            if (__any_sync(0xffffffffu, emax > TT)) {
                FULLROW(m0, s0, mt0, a0);
                FULLROW(m1, s1, mt1, a1);
                FULLROW(m2, s2, mt2, a2);
                FULLROW(m3, s3, mt3, a3);
            } else {
                s0 += ex2f_(e0 - TT);
                s1 += ex2f_(e1 - TT);
                s2 += ex2f_(e2 - TT);
                s3 += ex2f_(e3 - TT);
            }
        }
    }

#pragma unroll
    for (int off = 16; off; off >>= 1) {
        MERGEROW(m0, s0, off);
        MERGEROW(m1, s1, off);
        MERGEROW(m2, s2, off);
        MERGEROW(m3, s3, off);
    }

    if (lane == 0) {
        // lse2 = -pp*S2 + m + log2(s); pot = eps*(-lnN) - eps*ln2*lse2
        pout[row0 + 0] = fmaf(-EPSLN2, (-r0.w) + m0 + lg2f_(s0), EPSLOGMU);
        pout[row0 + 1] = fmaf(-EPSLN2, (-r1.w) + m1 + lg2f_(s1), EPSLOGMU);
        pout[row0 + 2] = fmaf(-EPSLN2, (-r2.w) + m2 + lg2f_(s2), EPSLOGMU);
        pout[row0 + 3] = fmaf(-EPSLN2, (-r3.w) + m3 + lg2f_(s3), EPSLOGMU);
    }
}

// Final pass: loss_partial = sum_{i,j} P_ij * C_ij for this block's rows.
__global__ void __launch_bounds__(256) loss_kernel() {
    int blk = blockIdx.x;
    int b = blk >> 6;
    int chunk = blk & 63;

    __shared__ float4 tbl[NN];
    __shared__ float  gg[NN];
    {
        const float4* Db = d_Q4 + b * NN;
        const float*  pb = d_g + b * NN;
        for (int j = threadIdx.x; j < NN; j += 256) {
            float4 q = Db[j];
            float gj = pb[j];
            float4 t;
            t.x = q.x * S2X2;
            t.y = q.y * S2X2;
            t.z = q.z * S2X2;
            t.w = fmaf(gj, S2F, -q.w);
            tbl[j] = t;
            gg[j] = gj;
        }
    }
    __syncthreads();

    int warp = threadIdx.x >> 5;
    int lane = threadIdx.x & 31;
    int row0 = b * NN + chunk * 32 + warp * 4;

    float4 r0 = d_P4[row0 + 0];
    float4 r1 = d_P4[row0 + 1];
    float4 r2 = d_P4[row0 + 2];
    float4 r3 = d_P4[row0 + 3];
    float fr0 = d_f[row0 + 0], fr1 = d_f[row0 + 1];
    float fr2 = d_f[row0 + 2], fr3 = d_f[row0 + 3];
    float ff0 = fmaf(fr0, S2F, -r0.w);
    float ff1 = fmaf(fr1, S2F, -r1.w);
    float ff2 = fmaf(fr2, S2F, -r2.w);
    float ff3 = fmaf(fr3, S2F, -r3.w);

    float part = 0.f;
#pragma unroll 2
    for (int k = 0; k < 64; ++k) {
        float4 q = tbl[(k << 5) + lane];
        float gj = gg[(k << 5) + lane];
        {
            float t = fmaf(r0.x, q.x, fmaf(r0.y, q.y, fmaf(r0.z, q.z, q.w)));
            float arg = ff0 + t;                       // (f+g-C)/(eps*ln2)
            float C = fmaf(-EPSLN2, arg, fr0 + gj);    // C = f+g - eps*ln2*arg
            part = fmaf(ex2f_(arg), C, part);
        }
        {
            float t = fmaf(r1.x, q.x, fmaf(r1.y, q.y, fmaf(r1.z, q.z, q.w)));
            float arg = ff1 + t;
            float C = fmaf(-EPSLN2, arg, fr1 + gj);
            part = fmaf(ex2f_(arg), C, part);
        }
        {
            float t = fmaf(r2.x, q.x, fmaf(r2.y, q.y, fmaf(r2.z, q.z, q.w)));
            float arg = ff2 + t;
            float C = fmaf(-EPSLN2, arg, fr2 + gj);
            part = fmaf(ex2f_(arg), C, part);
        }
        {
            float t = fmaf(r3.x, q.x, fmaf(r3.y, q.y, fmaf(r3.z, q.z, q.w)));
            float arg = ff3 + t;
            float C = fmaf(-EPSLN2, arg, fr3 + gj);
            part = fmaf(ex2f_(arg), C, part);
        }
    }

    __shared__ float red[256];
    red[threadIdx.x] = part;
    __syncthreads();
#pragma unroll
    for (int o = 128; o; o >>= 1) {
        if (threadIdx.x < o) red[threadIdx.x] += red[threadIdx.x + o];
        __syncthreads();
    }
    if (threadIdx.x == 0) d_partials[blockIdx.x] = red[0];
}

__global__ void reduce_kernel(float* __restrict__ out) {
    __shared__ float red[256];
    float v = 0.f;
    for (int i = threadIdx.x; i < 512; i += 256) v += d_partials[i];
    red[threadIdx.x] = v;
    __syncthreads();
#pragma unroll
    for (int o = 128; o; o >>= 1) {
        if (threadIdx.x < o) red[threadIdx.x] += red[threadIdx.x + o];
        __syncthreads();
    }
    // loss = mean_{b,i}( n * sum_j P*C ) = total / B
    if (threadIdx.x == 0) out[0] = red[0] * 0.125f;
}

extern "C" void kernel_launch(void* const* d_in, const int* in_sizes, int n_in,
                              void* d_out, int out_size) {
    const float* preds = (const float*)d_in[0];
    const float* gts   = (const float*)d_in[1];
    float* out = (float*)d_out;

    prep_kernel<<<BB, 256>>>(preds, gts);
    for (int it = 0; it < 50; ++it) {
        half_kernel<<<BB * 64, 256>>>(0);  // f-update (reduce over gts, uses g)
        half_kernel<<<BB * 64, 256>>>(1);  // g-update (reduce over preds, uses f)
    }
    loss_kernel<<<BB * 64, 256>>>();
    reduce_kernel<<<1, 256>>>(out);
}